// round 9
// baseline (speedup 1.0000x reference)
#include <cuda_runtime.h>

// Problem constants
#define BB 8
#define DD 1024
#define TT 2048
#define KK 8192          // codebook size
#define CDIM 8           // codebook dim
#define NTOK (BB*TT)     // 16384 tokens
#define NPAIR (KK/2)     // 4096 code pairs
#define CHUNK_PAIRS 512
#define NCHUNK (NPAIR/CHUNK_PAIRS)   // 8 chunks

typedef unsigned long long ull;
typedef long long ll;

// ---------------- scratch (static device globals; no runtime allocation) ----
__device__ float  g_enc[NTOK*CDIM];                    // normalized encodings
__device__ int    g_idx[NTOK];                         // argmax indices
__device__ __align__(16) float2 g_cbpack[NPAIR*CDIM];  // packed normalized codebook
__device__ __align__(16) float2 g_cninit[NPAIR];       // {-cn2_even/2, -cn2_odd/2}
__device__ float  g_wT[DD*CDIM];                       // w_in transposed [d][o]

// ---------------- f32x2 helpers (sm_100+/sm_103a packed fp32) ---------------
__device__ __forceinline__ ull pk2(float x, float y) {
    ull r; asm("mov.b64 %0, {%1,%2};" : "=l"(r) : "f"(x), "f"(y)); return r;
}
__device__ __forceinline__ void upk2(ull v, float& x, float& y) {
    asm("mov.b64 {%0,%1}, %2;" : "=f"(x), "=f"(y) : "l"(v));
}
__device__ __forceinline__ ull f2fma(ull a, ull b, ull c) {
    ull d; asm("fma.rn.f32x2 %0, %1, %2, %3;" : "=l"(d) : "l"(a), "l"(b), "l"(c));
    return d;
}

// ============================================================================
// K0: prep — normalize codebook, pack pairs for f32x2 search, transpose w_in,
//     zero the loss outputs. grid 16 x 256.
// ============================================================================
__global__ __launch_bounds__(256) void k0_prep(
    const float* __restrict__ w_in, const float* __restrict__ codebook,
    float* __restrict__ d_out, long long offLoss, int writeExtras)
{
    int g = blockIdx.x * blockDim.x + threadIdx.x;   // 0..4095

    for (int x = g; x < DD*CDIM; x += 4096) {
        int d = x >> 3, o = x & 7;
        g_wT[x] = w_in[o*DD + d];
    }

    if (writeExtras && g < 16) d_out[offLoss + g] = 0.0f;

    if (g < NPAIR) {
        int p = g;
        float a[8], b[8], an[8], bn[8];
        float sa = 0.f, sb = 0.f;
        #pragma unroll
        for (int k = 0; k < 8; k++) { a[k] = codebook[(2*p)*CDIM + k];   sa = fmaf(a[k], a[k], sa); }
        #pragma unroll
        for (int k = 0; k < 8; k++) { b[k] = codebook[(2*p+1)*CDIM + k]; sb = fmaf(b[k], b[k], sb); }
        float da = fmaxf(sqrtf(sa), 1e-12f);
        float db = fmaxf(sqrtf(sb), 1e-12f);
        float cn2a = 0.f, cn2b = 0.f;
        #pragma unroll
        for (int k = 0; k < 8; k++) {
            an[k] = a[k] / da; cn2a = fmaf(an[k], an[k], cn2a);
            bn[k] = b[k] / db; cn2b = fmaf(bn[k], bn[k], cn2b);
        }
        int c = p / CHUNK_PAIRS, r = p % CHUNK_PAIRS;
        int i = r >> 3, tx = r & 7;
        float2* dst = g_cbpack + c * (CHUNK_PAIRS * CDIM);
        #pragma unroll
        for (int k = 0; k < 8; k++) {
            int k2 = k >> 1, klo = k & 1;
            dst[((((i*4 + k2)*8) + tx) << 1) + klo] = make_float2(an[k], bn[k]);
        }
        g_cninit[p] = make_float2(-0.5f * cn2a, -0.5f * cn2b);
    }
}

// ============================================================================
// K1: z_e = w_in @ z + b_in; write z_e output; store normalized enc.
// grid 256 (8 b x 32 t-tiles of 64 tokens), block 256:
//   dthr = tid&15 (16 d-slices of 64), tthr = tid>>4 (16 groups x 4 tokens)
// LDG.128 over t (4 tokens); smem reduction with padded stride.
// ============================================================================
#define K1_RED 8704   // 64 tok * 129 + slack (floats); >= 8192 for w stage
__global__ __launch_bounds__(256, 2) void k1_encode(
    const float* __restrict__ z, const float* __restrict__ b_in,
    float* __restrict__ d_out, long long offZe, int writeExtras)
{
    __shared__ float s_mem[K1_RED];   // stage 1: w [d][o] (8192); stage 2: partials

    int tid = threadIdx.x;
    for (int x = tid; x < DD*CDIM; x += 256) s_mem[x] = g_wT[x];
    __syncthreads();

    int b = blockIdx.x >> 5;
    int tbase = (blockIdx.x & 31) * 64;
    int dthr = tid & 15, tthr = tid >> 4;
    int t0 = tbase + tthr * 4;

    const float* zp = z + (ll)b * DD * TT + t0;
    float acc[4][8];
    #pragma unroll
    for (int j = 0; j < 4; j++)
        #pragma unroll
        for (int o = 0; o < 8; o++) acc[j][o] = 0.f;

    int d0 = dthr * 64;
    #pragma unroll 4
    for (int d = d0; d < d0 + 64; d++) {
        float4 zv = *(const float4*)(zp + (ll)d * TT);
        float4 w0 = *(const float4*)(s_mem + d*8);
        float4 w1 = *(const float4*)(s_mem + d*8 + 4);
        float wv[8] = {w0.x,w0.y,w0.z,w0.w,w1.x,w1.y,w1.z,w1.w};
        #pragma unroll
        for (int o = 0; o < 8; o++) {
            acc[0][o] = fmaf(zv.x, wv[o], acc[0][o]);
            acc[1][o] = fmaf(zv.y, wv[o], acc[1][o]);
            acc[2][o] = fmaf(zv.z, wv[o], acc[2][o]);
            acc[3][o] = fmaf(zv.w, wv[o], acc[3][o]);
        }
    }
    __syncthreads();   // done reading w; reuse s_mem for partials

    #pragma unroll
    for (int j = 0; j < 4; j++) {
        int tl = tthr*4 + j;
        #pragma unroll
        for (int o = 0; o < 8; o++)
            s_mem[tl*129 + o*16 + dthr] = acc[j][o];
    }
    __syncthreads();

    if (tid < 64) {
        int tl = tid;
        float e[8];
        #pragma unroll
        for (int o = 0; o < 8; o++) {
            const float* p = s_mem + tl*129 + o*16;
            float s0 = (p[0]+p[1]) + (p[2]+p[3]);
            float s1 = (p[4]+p[5]) + (p[6]+p[7]);
            float s2 = (p[8]+p[9]) + (p[10]+p[11]);
            float s3 = (p[12]+p[13]) + (p[14]+p[15]);
            e[o] = ((s0+s1) + (s2+s3)) + b_in[o];
        }
        float ss = 0.f;
        #pragma unroll
        for (int o = 0; o < 8; o++) ss = fmaf(e[o], e[o], ss);
        float den = fmaxf(sqrtf(ss), 1e-12f);
        int t = tbase + tl;
        int tok = b * TT + t;
        #pragma unroll
        for (int o = 0; o < 8; o++) {
            if (writeExtras)
                d_out[offZe + ((ll)b*CDIM + o)*TT + t] = e[o];
            g_enc[tok*CDIM + o] = e[o] / den;
        }
    }
}

// ============================================================================
// K2: codebook argmax search. score = dot(enc_n, cb_n) - cn2/2, first-max wins.
// grid = 128 CTAs x 128 tokens, 256 threads (tx8 x ty32 x 4 tokens).
// ============================================================================
__global__ __launch_bounds__(256, 1) void k2_search(
    float* __restrict__ d_out, long long offIdx, int writeExtras)
{
    __shared__ __align__(16) float2 s_cb[CHUNK_PAIRS*CDIM];  // 32KB
    __shared__ __align__(16) float2 s_cn[CHUNK_PAIRS];       // 4KB

    int tid = threadIdx.x;
    int tx = tid & 7, ty = tid >> 3;
    int tokbase = blockIdx.x * 128 + ty * 4;

    ull ee[4][8];
    #pragma unroll
    for (int j = 0; j < 4; j++) {
        #pragma unroll
        for (int k = 0; k < 8; k++) {
            float e = g_enc[(tokbase + j)*CDIM + k];
            ee[j][k] = pk2(e, e);
        }
    }
    float best[4];
    int   bidx[4];
    #pragma unroll
    for (int j = 0; j < 4; j++) { best[j] = -3.402823466e38f; bidx[j] = 0; }

    for (int c = 0; c < NCHUNK; c++) {
        __syncthreads();
        {
            const uint4* src = (const uint4*)(g_cbpack + (ll)c * CHUNK_PAIRS * CDIM);
            uint4* dst = (uint4*)s_cb;
            #pragma unroll
            for (int u = tid; u < CHUNK_PAIRS*CDIM/2; u += 256) dst[u] = src[u];
            const uint4* srcn = (const uint4*)(g_cninit + (ll)c * CHUNK_PAIRS);
            ((uint4*)s_cn)[tid] = srcn[tid];
        }
        __syncthreads();

        #pragma unroll 2
        for (int i = 0; i < CHUNK_PAIRS/8; i++) {   // 64 iters
            ull cd[8];
            #pragma unroll
            for (int k2 = 0; k2 < 4; k2++) {
                ulonglong2 v = *(const ulonglong2*)(s_cb + ((((i*4 + k2)*8) + tx) << 1));
                cd[2*k2]     = v.x;
                cd[2*k2 + 1] = v.y;
            }
            ull cn = *(const ull*)(s_cn + (i*8 + tx));
            int pb = ((c * CHUNK_PAIRS + i*8 + tx) << 1);
            #pragma unroll
            for (int j = 0; j < 4; j++) {
                ull a = cn;
                #pragma unroll
                for (int k = 0; k < 8; k++) a = f2fma(ee[j][k], cd[k], a);
                float lo, hi; upk2(a, lo, hi);
                if (lo > best[j]) { best[j] = lo; bidx[j] = pb; }
                if (hi > best[j]) { best[j] = hi; bidx[j] = pb + 1; }
            }
        }
    }

    #pragma unroll
    for (int j = 0; j < 4; j++) {
        float bv = best[j]; int bi = bidx[j];
        #pragma unroll
        for (int m = 1; m < 8; m <<= 1) {
            float ov = __shfl_xor_sync(0xFFFFFFFFu, bv, m);
            int   oi = __shfl_xor_sync(0xFFFFFFFFu, bi, m);
            if (ov > bv || (ov == bv && oi < bi)) { bv = ov; bi = oi; }
        }
        if (tx == 0) {
            int tok = tokbase + j;
            g_idx[tok] = bi;
            if (writeExtras) d_out[offIdx + tok] = (float)bi;
        }
    }
}

// ============================================================================
// K3: out = w_out @ codebook[idx] + b_out.
// grid 256 (8 b x 32 t-tiles of 64), block 256:
//   tthr = tid&15 (x4 tokens), othr = tid>>4 (x64 o)
// 4 tokens/thread -> STG.128; 2 CTAs/SM.
// ============================================================================
__global__ __launch_bounds__(256, 2) void k3_decode(
    const float* __restrict__ w_out, const float* __restrict__ b_out,
    const float* __restrict__ codebook, float* __restrict__ out)
{
    __shared__ float s_w[DD*CDIM];   // 32KB, [o][k]
    __shared__ float s_b[DD];        // 4KB

    int tid = threadIdx.x;
    for (int x = tid; x < DD*CDIM; x += 256) s_w[x] = w_out[x];
    for (int x = tid; x < DD;      x += 256) s_b[x] = b_out[x];
    __syncthreads();

    int b = blockIdx.x >> 5;
    int tbase = (blockIdx.x & 31) * 64;
    int tthr = tid & 15, othr = tid >> 4;
    int t0 = tbase + tthr * 4;
    int tok0 = b * TT + t0;

    // gather 4 codebook rows (unnormalized)
    float cv[4][8];
    #pragma unroll
    for (int j = 0; j < 4; j++) {
        int idx = g_idx[tok0 + j];
        const float* cp = codebook + (ll)idx * CDIM;
        float4 ca = *(const float4*)cp;
        float4 cb = *(const float4*)(cp + 4);
        cv[j][0]=ca.x; cv[j][1]=ca.y; cv[j][2]=ca.z; cv[j][3]=ca.w;
        cv[j][4]=cb.x; cv[j][5]=cb.y; cv[j][6]=cb.z; cv[j][7]=cb.w;
    }

    ll obase = (ll)b * DD * TT + t0;
    int o0 = othr * 64;
    #pragma unroll 4
    for (int o = o0; o < o0 + 64; o++) {
        float4 w0 = *(const float4*)(s_w + o*8);
        float4 w1 = *(const float4*)(s_w + o*8 + 4);
        float wv[8] = {w0.x,w0.y,w0.z,w0.w,w1.x,w1.y,w1.z,w1.w};
        float bias = s_b[o];
        float r[4];
        #pragma unroll
        for (int j = 0; j < 4; j++) {
            float a = bias;
            #pragma unroll
            for (int k = 0; k < 8; k++) a = fmaf(cv[j][k], wv[k], a);
            r[j] = a;
        }
        *(float4*)(out + obase + (ll)o * TT) = make_float4(r[0], r[1], r[2], r[3]);
    }
}

// ============================================================================
extern "C" void kernel_launch(void* const* d_in, const int* in_sizes, int n_in,
                              void* d_out, int out_size)
{
    const float* z        = (const float*)d_in[0];
    const float* w_in     = (const float*)d_in[1];
    const float* b_in     = (const float*)d_in[2];
    const float* w_out    = (const float*)d_in[3];
    const float* b_out    = (const float*)d_in[4];
    const float* codebook = (const float*)d_in[5];
    float* out = (float*)d_out;

    long long nOut   = (long long)BB * DD * TT;       // 16,777,216
    long long offLoss = nOut;
    long long offIdx  = nOut + 16;
    long long offZe   = nOut + 16 + NTOK;
    long long total   = offZe + (long long)NTOK * CDIM;
    int writeExtras = ((long long)out_size >= total) ? 1 : 0;

    k0_prep  <<<16,  256>>>(w_in, codebook, out, offLoss, writeExtras);
    k1_encode<<<256, 256>>>(z, b_in, out, offZe, writeExtras);
    k2_search<<<128, 256>>>(out, offIdx, writeExtras);
    k3_decode<<<256, 256>>>(w_out, b_out, codebook, out);
}

// round 11
// speedup vs baseline: 1.1230x; 1.1230x over previous
#include <cuda_runtime.h>

// Problem constants
#define BB 8
#define DD 1024
#define TT 2048
#define KK 8192          // codebook size
#define CDIM 8           // codebook dim
#define NTOK (BB*TT)     // 16384 tokens
#define NPAIR (KK/2)     // 4096 code pairs
#define CHUNK_PAIRS 512
#define NCHUNK (NPAIR/CHUNK_PAIRS)   // 8 chunks

typedef unsigned long long ull;
typedef long long ll;

// ---------------- scratch (static device globals; no runtime allocation) ----
__device__ float  g_enc[NTOK*CDIM];                    // normalized encodings
__device__ int    g_idx[NTOK];                         // argmax indices
__device__ __align__(16) float2 g_cbpack[NPAIR*CDIM];  // packed normalized codebook
__device__ __align__(16) float2 g_cninit[NPAIR];       // {-cn2_even/2, -cn2_odd/2}
__device__ float  g_wT[DD*CDIM];                       // w_in transposed [d][o]

// ---------------- f32x2 helpers (sm_100+/sm_103a packed fp32) ---------------
__device__ __forceinline__ ull pk2(float x, float y) {
    ull r; asm("mov.b64 %0, {%1,%2};" : "=l"(r) : "f"(x), "f"(y)); return r;
}
__device__ __forceinline__ void upk2(ull v, float& x, float& y) {
    asm("mov.b64 {%0,%1}, %2;" : "=f"(x), "=f"(y) : "l"(v));
}
__device__ __forceinline__ ull f2fma(ull a, ull b, ull c) {
    ull d; asm("fma.rn.f32x2 %0, %1, %2, %3;" : "=l"(d) : "l"(a), "l"(b), "l"(c));
    return d;
}

// ============================================================================
// K0: prep — normalize codebook, pack pairs for f32x2 search, transpose w_in,
//     zero the loss outputs. grid 16 x 256.
// ============================================================================
__global__ __launch_bounds__(256) void k0_prep(
    const float* __restrict__ w_in, const float* __restrict__ codebook,
    float* __restrict__ d_out, long long offLoss, int writeExtras)
{
    int g = blockIdx.x * blockDim.x + threadIdx.x;   // 0..4095

    for (int x = g; x < DD*CDIM; x += 4096) {
        int d = x >> 3, o = x & 7;
        g_wT[x] = w_in[o*DD + d];
    }

    if (writeExtras && g < 16) d_out[offLoss + g] = 0.0f;

    if (g < NPAIR) {
        int p = g;
        float a[8], b[8], an[8], bn[8];
        float sa = 0.f, sb = 0.f;
        #pragma unroll
        for (int k = 0; k < 8; k++) { a[k] = codebook[(2*p)*CDIM + k];   sa = fmaf(a[k], a[k], sa); }
        #pragma unroll
        for (int k = 0; k < 8; k++) { b[k] = codebook[(2*p+1)*CDIM + k]; sb = fmaf(b[k], b[k], sb); }
        float da = fmaxf(sqrtf(sa), 1e-12f);
        float db = fmaxf(sqrtf(sb), 1e-12f);
        float cn2a = 0.f, cn2b = 0.f;
        #pragma unroll
        for (int k = 0; k < 8; k++) {
            an[k] = a[k] / da; cn2a = fmaf(an[k], an[k], cn2a);
            bn[k] = b[k] / db; cn2b = fmaf(bn[k], bn[k], cn2b);
        }
        int c = p / CHUNK_PAIRS, r = p % CHUNK_PAIRS;
        int i = r >> 3, tx = r & 7;
        float2* dst = g_cbpack + c * (CHUNK_PAIRS * CDIM);
        #pragma unroll
        for (int k = 0; k < 8; k++) {
            int k2 = k >> 1, klo = k & 1;
            dst[((((i*4 + k2)*8) + tx) << 1) + klo] = make_float2(an[k], bn[k]);
        }
        g_cninit[p] = make_float2(-0.5f * cn2a, -0.5f * cn2b);
    }
}

// ============================================================================
// K1: z_e = w_in @ z + b_in; write z_e output; store normalized enc.
// COALESCED-over-t scalar loads (R2 structure) + higher occupancy:
// grid 512 (8 b x 64 t-tiles of 32 tokens), block 256:
//   tl = tid&31 -> token (lanes span t: 1 line per LDG), ds = tid>>5 -> d-slice
// ============================================================================
__global__ __launch_bounds__(256, 3) void k1_encode(
    const float* __restrict__ z, const float* __restrict__ b_in,
    float* __restrict__ d_out, long long offZe, int writeExtras)
{
    __shared__ float s_w[DD*CDIM];     // 32KB, [d][o]
    __shared__ float s_red[256*8];     // 8KB partials

    int tid = threadIdx.x;
    for (int x = tid; x < DD*CDIM; x += 256) s_w[x] = g_wT[x];
    __syncthreads();

    int b = blockIdx.x >> 6;
    int tbase = (blockIdx.x & 63) * 32;
    int tl = tid & 31, ds = tid >> 5;   // 8 d-slices of 128
    int t = tbase + tl;

    const float* zp = z + (ll)b * DD * TT + t;
    float acc[8] = {0.f,0.f,0.f,0.f,0.f,0.f,0.f,0.f};
    int d0 = ds * 128;
    #pragma unroll 8
    for (int d = d0; d < d0 + 128; d++) {
        float zv = zp[(ll)d * TT];
        float4 w0 = *(const float4*)(s_w + d*8);
        float4 w1 = *(const float4*)(s_w + d*8 + 4);
        acc[0] = fmaf(zv, w0.x, acc[0]);
        acc[1] = fmaf(zv, w0.y, acc[1]);
        acc[2] = fmaf(zv, w0.z, acc[2]);
        acc[3] = fmaf(zv, w0.w, acc[3]);
        acc[4] = fmaf(zv, w1.x, acc[4]);
        acc[5] = fmaf(zv, w1.y, acc[5]);
        acc[6] = fmaf(zv, w1.z, acc[6]);
        acc[7] = fmaf(zv, w1.w, acc[7]);
    }
    #pragma unroll
    for (int o = 0; o < 8; o++) s_red[tid*8 + o] = acc[o];
    __syncthreads();

    if (tid < 32) {
        float e[8];
        #pragma unroll
        for (int o = 0; o < 8; o++) {
            float s0 = (s_red[(0*32+tid)*8+o] + s_red[(1*32+tid)*8+o])
                     + (s_red[(2*32+tid)*8+o] + s_red[(3*32+tid)*8+o]);
            float s1 = (s_red[(4*32+tid)*8+o] + s_red[(5*32+tid)*8+o])
                     + (s_red[(6*32+tid)*8+o] + s_red[(7*32+tid)*8+o]);
            e[o] = (s0 + s1) + b_in[o];
        }
        float ss = 0.f;
        #pragma unroll
        for (int o = 0; o < 8; o++) ss = fmaf(e[o], e[o], ss);
        float den = fmaxf(sqrtf(ss), 1e-12f);
        int tt = tbase + tid;
        int tok = b * TT + tt;
        #pragma unroll
        for (int o = 0; o < 8; o++) {
            if (writeExtras)
                d_out[offZe + ((ll)b*CDIM + o)*TT + tt] = e[o];
            g_enc[tok*CDIM + o] = e[o] / den;
        }
    }
}

// ============================================================================
// K2: codebook argmax search. score = dot(enc_n, cb_n) - cn2/2, first-max wins.
// grid = 128 CTAs x 128 tokens, 256 threads (tx8 x ty32 x 4 tokens).
// ============================================================================
__global__ __launch_bounds__(256, 1) void k2_search(
    float* __restrict__ d_out, long long offIdx, int writeExtras)
{
    __shared__ __align__(16) float2 s_cb[CHUNK_PAIRS*CDIM];  // 32KB
    __shared__ __align__(16) float2 s_cn[CHUNK_PAIRS];       // 4KB

    int tid = threadIdx.x;
    int tx = tid & 7, ty = tid >> 3;
    int tokbase = blockIdx.x * 128 + ty * 4;

    ull ee[4][8];
    #pragma unroll
    for (int j = 0; j < 4; j++) {
        #pragma unroll
        for (int k = 0; k < 8; k++) {
            float e = g_enc[(tokbase + j)*CDIM + k];
            ee[j][k] = pk2(e, e);
        }
    }
    float best[4];
    int   bidx[4];
    #pragma unroll
    for (int j = 0; j < 4; j++) { best[j] = -3.402823466e38f; bidx[j] = 0; }

    for (int c = 0; c < NCHUNK; c++) {
        __syncthreads();
        {
            const uint4* src = (const uint4*)(g_cbpack + (ll)c * CHUNK_PAIRS * CDIM);
            uint4* dst = (uint4*)s_cb;
            #pragma unroll
            for (int u = tid; u < CHUNK_PAIRS*CDIM/2; u += 256) dst[u] = src[u];
            const uint4* srcn = (const uint4*)(g_cninit + (ll)c * CHUNK_PAIRS);
            ((uint4*)s_cn)[tid] = srcn[tid];
        }
        __syncthreads();

        #pragma unroll 2
        for (int i = 0; i < CHUNK_PAIRS/8; i++) {   // 64 iters
            ull cd[8];
            #pragma unroll
            for (int k2 = 0; k2 < 4; k2++) {
                ulonglong2 v = *(const ulonglong2*)(s_cb + ((((i*4 + k2)*8) + tx) << 1));
                cd[2*k2]     = v.x;
                cd[2*k2 + 1] = v.y;
            }
            ull cn = *(const ull*)(s_cn + (i*8 + tx));
            int pb = ((c * CHUNK_PAIRS + i*8 + tx) << 1);
            #pragma unroll
            for (int j = 0; j < 4; j++) {
                ull a = cn;
                #pragma unroll
                for (int k = 0; k < 8; k++) a = f2fma(ee[j][k], cd[k], a);
                float lo, hi; upk2(a, lo, hi);
                if (lo > best[j]) { best[j] = lo; bidx[j] = pb; }
                if (hi > best[j]) { best[j] = hi; bidx[j] = pb + 1; }
            }
        }
    }

    #pragma unroll
    for (int j = 0; j < 4; j++) {
        float bv = best[j]; int bi = bidx[j];
        #pragma unroll
        for (int m = 1; m < 8; m <<= 1) {
            float ov = __shfl_xor_sync(0xFFFFFFFFu, bv, m);
            int   oi = __shfl_xor_sync(0xFFFFFFFFu, bi, m);
            if (ov > bv || (ov == bv && oi < bi)) { bv = ov; bi = oi; }
        }
        if (tx == 0) {
            int tok = tokbase + j;
            g_idx[tok] = bi;
            if (writeExtras) d_out[offIdx + tok] = (float)bi;
        }
    }
}

// ============================================================================
// K3: out = w_out @ codebook[idx] + b_out.
// grid 512 (256 t-tiles x 2 o-halves), block 256:
//   tthr = tid&15 (x4 tokens -> STG.128), othr = tid>>4 (x32 o)
// f32x2 fma pairing tokens {0,1} and {2,3}; 16KB w-half smem for occupancy.
// ============================================================================
__global__ __launch_bounds__(256, 3) void k3_decode(
    const float* __restrict__ w_out, const float* __restrict__ b_out,
    const float* __restrict__ codebook, float* __restrict__ out)
{
    __shared__ float s_w[512*CDIM];  // 16KB: this CTA's 512-row o-half
    __shared__ float s_b[512];       // 2KB

    int tid = threadIdx.x;
    int bx = blockIdx.x;
    int ohalf = bx & 1;
    int tile  = bx >> 1;             // 0..255
    int b = tile >> 5;
    int tbase = (tile & 31) * 64;
    int obase = ohalf * 512;

    for (int x = tid; x < 512*CDIM; x += 256) s_w[x] = w_out[obase*CDIM + x];
    for (int x = tid; x < 512;      x += 256) s_b[x] = b_out[obase + x];
    __syncthreads();

    int tthr = tid & 15, othr = tid >> 4;
    int t0 = tbase + tthr * 4;
    int tok0 = b * TT + t0;

    // gather 4 codebook rows, pack token pairs for f32x2
    ull c01[8], c23[8];
    {
        float cv[4][8];
        #pragma unroll
        for (int j = 0; j < 4; j++) {
            int idx = g_idx[tok0 + j];
            const float* cp = codebook + (ll)idx * CDIM;
            float4 ca = *(const float4*)cp;
            float4 cb = *(const float4*)(cp + 4);
            cv[j][0]=ca.x; cv[j][1]=ca.y; cv[j][2]=ca.z; cv[j][3]=ca.w;
            cv[j][4]=cb.x; cv[j][5]=cb.y; cv[j][6]=cb.z; cv[j][7]=cb.w;
        }
        #pragma unroll
        for (int k = 0; k < 8; k++) {
            c01[k] = pk2(cv[0][k], cv[1][k]);
            c23[k] = pk2(cv[2][k], cv[3][k]);
        }
    }

    ll gbase = (ll)b * DD * TT + t0;
    int ol0 = othr * 32;            // local o within the 512-half
    #pragma unroll 4
    for (int ol = ol0; ol < ol0 + 32; ol++) {
        float4 w0 = *(const float4*)(s_w + ol*8);
        float4 w1 = *(const float4*)(s_w + ol*8 + 4);
        float wv[8] = {w0.x,w0.y,w0.z,w0.w,w1.x,w1.y,w1.z,w1.w};
        float bias = s_b[ol];
        ull a01 = pk2(bias, bias);
        ull a23 = a01;
        #pragma unroll
        for (int k = 0; k < 8; k++) {
            ull ww = pk2(wv[k], wv[k]);
            a01 = f2fma(c01[k], ww, a01);
            a23 = f2fma(c23[k], ww, a23);
        }
        float r0, r1, r2, r3;
        upk2(a01, r0, r1);
        upk2(a23, r2, r3);
        *(float4*)(out + gbase + (ll)(obase + ol) * TT) = make_float4(r0, r1, r2, r3);
    }
}

// ============================================================================
extern "C" void kernel_launch(void* const* d_in, const int* in_sizes, int n_in,
                              void* d_out, int out_size)
{
    const float* z        = (const float*)d_in[0];
    const float* w_in     = (const float*)d_in[1];
    const float* b_in     = (const float*)d_in[2];
    const float* w_out    = (const float*)d_in[3];
    const float* b_out    = (const float*)d_in[4];
    const float* codebook = (const float*)d_in[5];
    float* out = (float*)d_out;

    long long nOut   = (long long)BB * DD * TT;       // 16,777,216
    long long offLoss = nOut;
    long long offIdx  = nOut + 16;
    long long offZe   = nOut + 16 + NTOK;
    long long total   = offZe + (long long)NTOK * CDIM;
    int writeExtras = ((long long)out_size >= total) ? 1 : 0;

    k0_prep  <<<16,  256>>>(w_in, codebook, out, offLoss, writeExtras);
    k1_encode<<<512, 256>>>(z, b_in, out, offZe, writeExtras);
    k2_search<<<128, 256>>>(out, offIdx, writeExtras);
    k3_decode<<<512, 256>>>(w_out, b_out, codebook, out);
}